// round 6
// baseline (speedup 1.0000x reference)
#include <cuda_runtime.h>
#include <math.h>

#define BB 16
#define EE 4
#define DIMC 64
#define RR 32
#define HH 128
#define WW 128
#define HWPX (HH*WW)
#define FREQN 64
#define NPAIR (BB*EE)

typedef unsigned long long ull;

// ---- packed f32x2 helpers (sm_100+) ----
__device__ __forceinline__ ull pk2(float lo, float hi) {
    ull r;
    asm("mov.b64 %0, {%1, %2};" : "=l"(r) : "f"(lo), "f"(hi));
    return r;
}
__device__ __forceinline__ void fma2(ull& d, ull a, ull b) {
    asm("fma.rn.f32x2 %0, %1, %2, %0;" : "+l"(d) : "l"(a), "l"(b));
}
__device__ __forceinline__ float2 upk(ull v) {
    float lo, hi;
    asm("mov.b64 {%0, %1}, %2;" : "=f"(lo), "=f"(hi) : "l"(v));
    return make_float2(lo, hi);
}

// ---------------- scratch (device globals) ----------------
__device__ float d_pooled[BB][DIMC];
__device__ float d_gates[BB][EE];
__device__ float d_gatesum[BB];
__device__ int   d_topidx[BB][2];
__device__ float d_qc[EE][RR][DIMC];
__device__ float d_kvc[EE][2*RR][DIMC];
__device__ float d_qpre[NPAIR][RR][HWPX];
__device__ float d_kvpre[NPAIR][2*RR][HWPX];
__device__ float d_qb[NPAIR][RR][HWPX];
__device__ float d_kb[NPAIR][RR][HWPX];
__device__ float d_vb[NPAIR][RR][HWPX];
__device__ float d_gact[NPAIR][RR][HWPX];
__device__ float d_attb[NPAIR][RR][HWPX];

// ---------------- K0: pooled mean ----------------
__global__ void k_pool(const float* __restrict__ x) {
    int bc = blockIdx.x;
    const float* p = x + (size_t)bc * HWPX;
    float s = 0.f;
    for (int i = threadIdx.x; i < HWPX; i += 256) s += p[i];
    __shared__ float sm[256];
    sm[threadIdx.x] = s;
    __syncthreads();
    for (int o = 128; o > 0; o >>= 1) {
        if (threadIdx.x < o) sm[threadIdx.x] += sm[threadIdx.x + o];
        __syncthreads();
    }
    if (threadIdx.x == 0) d_pooled[bc / DIMC][bc % DIMC] = sm[0] * (1.f / (float)HWPX);
}

// ---------------- K1: gating ----------------
__global__ void k_gate(const float* __restrict__ freq_emb, const float* __restrict__ noise,
                       const float* __restrict__ gate_w, const float* __restrict__ fgw) {
    int b = threadIdx.x;
    if (b >= BB) return;
    float lg[EE];
    for (int e = 0; e < EE; e++) {
        float s = 0.f;
        for (int d = 0; d < DIMC; d++) s += d_pooled[b][d] * gate_w[e * DIMC + d];
        for (int f = 0; f < FREQN; f++) s += freq_emb[b * FREQN + f] * fgw[e * FREQN + f];
        lg[e] = s + noise[b * EE + e] * (1.0f / (float)EE);
    }
    float mx = lg[0];
    for (int e = 1; e < EE; e++) mx = fmaxf(mx, lg[e]);
    float se = 0.f, sc[EE];
    for (int e = 0; e < EE; e++) { sc[e] = expf(lg[e] - mx); se += sc[e]; }
    for (int e = 0; e < EE; e++) sc[e] /= se;
    int i1 = 0;
    for (int e = 1; e < EE; e++) if (sc[e] > sc[i1]) i1 = e;
    int i2 = -1;
    for (int e = 0; e < EE; e++) {
        if (e == i1) continue;
        if (i2 < 0 || sc[e] > sc[i2]) i2 = e;
    }
    for (int e = 0; e < EE; e++) d_gates[b][e] = (e == i1 || e == i2) ? sc[e] : 0.f;
    d_gatesum[b] = sc[i1] + sc[i2];
    d_topidx[b][0] = i1;
    d_topidx[b][1] = i2;
}

// ---------------- K2: compose q_w@p0, kv_w@p0 ----------------
__global__ void k_compose(const float* __restrict__ p0, const float* __restrict__ q_w,
                          const float* __restrict__ kv_w) {
    int e = blockIdx.x;
    __shared__ float sp0[RR][DIMC];
    for (int i = threadIdx.x; i < RR * DIMC; i += 256)
        sp0[i / DIMC][i % DIMC] = p0[e * RR * DIMC + i];
    __syncthreads();
    for (int i = threadIdx.x; i < RR * DIMC; i += 256) {
        int o = i / DIMC, d = i % DIMC;
        float s = 0.f;
        for (int c = 0; c < RR; c++) s += q_w[(e * RR + o) * RR + c] * sp0[c][d];
        d_qc[e][o][d] = s;
    }
    for (int i = threadIdx.x; i < 2 * RR * DIMC; i += 256) {
        int o = i / DIMC, d = i % DIMC;
        float s = 0.f;
        for (int c = 0; c < RR; c++) s += kv_w[(e * 2 * RR + o) * RR + c] * sp0[c][d];
        d_kvc[e][o][d] = s;
    }
}

// ---------------- K3: per-pixel matmuls, warp-partitioned outputs + f32x2 ----------------
// Block = 64-px tile, 8 warps. Warp w owns outputs [w*12, w*12+12) (pass1) /
// [w*4, w*4+4) (pass2); lane owns 2 px. Weight LDS is broadcast and NOT
// replicated across warps; x is staged pre-packed as f32x2 d-pairs.
#define PXT 64
__global__ __launch_bounds__(256) void k_pre(const float* __restrict__ x,
                                             const float* __restrict__ shin,
                                             const float* __restrict__ p1) {
    __shared__ __align__(16) float ws[96 * DIMC];   // 24KB, [o][d]
    __shared__ __align__(16) ull  xs2[32 * PXT];    // 16KB, [dp][px] packed {x[2dp],x[2dp+1]}
    int pair = blockIdx.y;
    int b = pair / EE, e = pair % EE;
    if (d_gates[b][e] == 0.f) return;
    int t = threadIdx.x;
    int warp = t >> 5, lane = t & 31;
    int pxb = blockIdx.x * PXT;

    // stage weights (96 rows: 32 q + 64 kv)
    for (int i = t; i < 96 * DIMC; i += 256)
        ws[i] = (i < RR * DIMC) ? (&d_qc[e][0][0])[i] : (&d_kvc[e][0][0])[i - RR * DIMC];

    // stage x tile, packed over d-pairs
    {
        const float* xb = x + (size_t)b * DIMC * HWPX + pxb;
        int p2 = lane * 2;
        for (int dp = warp; dp < 32; dp += 8) {
            float2 a = *(const float2*)&xb[(size_t)(2 * dp) * HWPX + p2];
            float2 c = *(const float2*)&xb[(size_t)(2 * dp + 1) * HWPX + p2];
            xs2[dp * PXT + p2]     = pk2(a.x, c.x);
            xs2[dp * PXT + p2 + 1] = pk2(a.y, c.y);
        }
    }
    __syncthreads();

    // pass1: 12 outs per warp, 2 px per lane
    {
        int o0 = warp * 12;
        ull acc[12][2];
#pragma unroll
        for (int k = 0; k < 12; k++) { acc[k][0] = 0ull; acc[k][1] = 0ull; }
#pragma unroll 4
        for (int dp2 = 0; dp2 < 16; dp2++) {
            ull xa0 = xs2[(2 * dp2) * PXT + lane * 2];
            ull xa1 = xs2[(2 * dp2) * PXT + lane * 2 + 1];
            ull xb0 = xs2[(2 * dp2 + 1) * PXT + lane * 2];
            ull xb1 = xs2[(2 * dp2 + 1) * PXT + lane * 2 + 1];
#pragma unroll
            for (int k = 0; k < 12; k++) {
                ulonglong2 w2 = *(const ulonglong2*)&ws[(o0 + k) * DIMC + dp2 * 4];
                fma2(acc[k][0], xa0, w2.x);
                fma2(acc[k][1], xa1, w2.x);
                fma2(acc[k][0], xb0, w2.y);
                fma2(acc[k][1], xb1, w2.y);
            }
        }
#pragma unroll
        for (int k = 0; k < 12; k++) {
            int o = o0 + k;
            float2 r0 = upk(acc[k][0]), r1 = upk(acc[k][1]);
            float* dst = (o < RR) ? &d_qpre[pair][o][0] : &d_kvpre[pair][o - RR][0];
            *(float2*)&dst[pxb + lane * 2] = make_float2(r0.x + r0.y, r1.x + r1.y);
        }
    }
    __syncthreads();

    // reload: ws <- p1 (32 rows), xs2 <- shared input
    for (int i = t; i < RR * DIMC; i += 256) ws[i] = p1[e * RR * DIMC + i];
    {
        const float* sb = shin + (size_t)b * DIMC * HWPX + pxb;
        int p2 = lane * 2;
        for (int dp = warp; dp < 32; dp += 8) {
            float2 a = *(const float2*)&sb[(size_t)(2 * dp) * HWPX + p2];
            float2 c = *(const float2*)&sb[(size_t)(2 * dp + 1) * HWPX + p2];
            xs2[dp * PXT + p2]     = pk2(a.x, c.x);
            xs2[dp * PXT + p2 + 1] = pk2(a.y, c.y);
        }
    }
    __syncthreads();

    // pass2: 4 outs per warp, silu
    {
        int o0 = warp * 4;
        ull acc[4][2];
#pragma unroll
        for (int k = 0; k < 4; k++) { acc[k][0] = 0ull; acc[k][1] = 0ull; }
#pragma unroll 4
        for (int dp2 = 0; dp2 < 16; dp2++) {
            ull xa0 = xs2[(2 * dp2) * PXT + lane * 2];
            ull xa1 = xs2[(2 * dp2) * PXT + lane * 2 + 1];
            ull xb0 = xs2[(2 * dp2 + 1) * PXT + lane * 2];
            ull xb1 = xs2[(2 * dp2 + 1) * PXT + lane * 2 + 1];
#pragma unroll
            for (int k = 0; k < 4; k++) {
                ulonglong2 w2 = *(const ulonglong2*)&ws[(o0 + k) * DIMC + dp2 * 4];
                fma2(acc[k][0], xa0, w2.x);
                fma2(acc[k][1], xa1, w2.x);
                fma2(acc[k][0], xb0, w2.y);
                fma2(acc[k][1], xb1, w2.y);
            }
        }
#pragma unroll
        for (int k = 0; k < 4; k++) {
            float2 r0 = upk(acc[k][0]), r1 = upk(acc[k][1]);
            float s0 = r0.x + r0.y, s1 = r1.x + r1.y;
            s0 = s0 / (1.f + expf(-s0));
            s1 = s1 / (1.f + expf(-s1));
            *(float2*)&d_gact[pair][o0 + k][pxb + lane * 2] = make_float2(s0, s1);
        }
    }
}

// ---------------- K4: depthwise conv, 32x32 tiles, 4 rows/thread ----------------
template <int R>
__device__ __forceinline__ void dwconv_tile(const float* __restrict__ src,
                                            const float* __restrict__ w,
                                            float* __restrict__ dst,
                                            int ty, int tx, float* tile) {
    const int KS = 2 * R + 1, TW = 32 + 2 * R;
    int t = threadIdx.x;
    for (int i = t; i < TW * TW; i += 256) {
        int iy = i / TW, ix = i % TW;
        int gy = ty + iy - R, gx = tx + ix - R;
        tile[i] = (gy >= 0 && gy < HH && gx >= 0 && gx < WW) ? src[gy * WW + gx] : 0.f;
    }
    float wr[KS * KS];
#pragma unroll
    for (int i = 0; i < KS * KS; i++) wr[i] = w[i];
    __syncthreads();
    int lx = t % 32, y0 = (t / 32) * 4;
    float acc[4] = {0.f, 0.f, 0.f, 0.f};
#pragma unroll
    for (int dx = 0; dx < KS; dx++) {
        float col[4 + 2 * R];
#pragma unroll
        for (int r = 0; r < 4 + 2 * R; r++) col[r] = tile[(y0 + r) * TW + lx + dx];
#pragma unroll
        for (int dy = 0; dy < KS; dy++)
#pragma unroll
            for (int oy = 0; oy < 4; oy++) acc[oy] += wr[dy * KS + dx] * col[oy + dy];
    }
#pragma unroll
    for (int oy = 0; oy < 4; oy++) dst[(ty + y0 + oy) * WW + tx + lx] = acc[oy];
}

__global__ __launch_bounds__(256) void k_dw(const float* __restrict__ q_dw,
                                            const float* __restrict__ kv_dw) {
    int pair = blockIdx.z;
    int b = pair / EE, e = pair % EE;
    if (d_gates[b][e] == 0.f) return;
    __shared__ float tile[38 * 38];
    int ch = blockIdx.y;
    int ty = (blockIdx.x >> 2) * 32, tx = (blockIdx.x & 3) * 32;
    if (ch < RR) {
        dwconv_tile<1>(&d_qpre[pair][ch][0], q_dw + (size_t)(e * RR + ch) * 9,
                       &d_qb[pair][ch][0], ty, tx, tile);
    } else {
        int c = ch - RR;
        float* dst = (c < RR) ? &d_kb[pair][c][0] : &d_vb[pair][c - RR][0];
        dwconv_tile<3>(&d_kvpre[pair][c][0], kv_dw + (size_t)(e * 2 * RR + c) * 49,
                       dst, ty, tx, tile);
    }
}

// ---------------- K5: 8x8 circular conv + LN + *v + po conv ----------------
__global__ __launch_bounds__(256) void k_patch(const float* __restrict__ ln_w,
                                               const float* __restrict__ ln_b,
                                               const float* __restrict__ po_w,
                                               const float* __restrict__ po_b) {
    int pair = blockIdx.y;
    int b = pair / EE, e = pair % EE;
    if (d_gates[b][e] == 0.f) return;
    int patch = blockIdx.x;
    int r0 = (patch / 16) * 8, c0 = (patch % 16) * 8;
    int t = threadIdx.x;

    __shared__ float sq[RR * 72];
    __shared__ float sk[RR * 72];
    __shared__ float sv[RR * 72];
    __shared__ float spw[RR * 33];
    __shared__ float spb[RR], slw[RR], slb[RR];

    {
        int c = t >> 3, pr = t & 7;
        size_t off = (size_t)(r0 + pr) * WW + c0;
        const float* qp = &d_qb[pair][c][off];
        const float* kp = &d_kb[pair][c][off];
        const float* vp = &d_vb[pair][c][off];
        *(float4*)&sq[c * 72 + pr * 8]     = *(const float4*)qp;
        *(float4*)&sq[c * 72 + pr * 8 + 4] = *(const float4*)(qp + 4);
        *(float4*)&sk[c * 72 + pr * 8]     = *(const float4*)kp;
        *(float4*)&sk[c * 72 + pr * 8 + 4] = *(const float4*)(kp + 4);
        *(float4*)&sv[c * 72 + pr * 8]     = *(const float4*)vp;
        *(float4*)&sv[c * 72 + pr * 8 + 4] = *(const float4*)(vp + 4);
    }
    for (int i = t; i < RR * RR; i += 256)
        spw[(i / RR) * 33 + (i % RR)] = po_w[(size_t)e * RR * RR + i];
    if (t < RR) {
        spb[t] = po_b[e * RR + t];
        slw[t] = ln_w[e * RR + t];
        slb[t] = ln_b[e * RR + t];
    }
    __syncthreads();

    int c = t >> 3, i = t & 7;
    float acc[8];
#pragma unroll
    for (int j = 0; j < 8; j++) acc[j] = 0.f;
#pragma unroll
    for (int u = 0; u < 8; u++) {
        float4 qa = *(const float4*)&sq[c * 72 + u * 8];
        float4 qb4 = *(const float4*)&sq[c * 72 + u * 8 + 4];
        float qv[8] = {qa.x, qa.y, qa.z, qa.w, qb4.x, qb4.y, qb4.z, qb4.w};
        int kr = (i - u) & 7;
        float4 ka = *(const float4*)&sk[c * 72 + kr * 8];
        float4 kb4 = *(const float4*)&sk[c * 72 + kr * 8 + 4];
        float kv[8] = {ka.x, ka.y, ka.z, ka.w, kb4.x, kb4.y, kb4.z, kb4.w};
#pragma unroll
        for (int j = 0; j < 8; j++)
#pragma unroll
            for (int v = 0; v < 8; v++) acc[j] += qv[v] * kv[(j - v) & 7];
    }
    __syncthreads();
    *(float4*)&sq[c * 72 + i * 8]     = make_float4(acc[0], acc[1], acc[2], acc[3]);
    *(float4*)&sq[c * 72 + i * 8 + 4] = make_float4(acc[4], acc[5], acc[6], acc[7]);
    __syncthreads();

    if (t < 64) {
        float mu = 0.f;
#pragma unroll
        for (int c2 = 0; c2 < RR; c2++) mu += sq[c2 * 72 + t];
        mu *= (1.f / RR);
        float var = 0.f;
#pragma unroll
        for (int c2 = 0; c2 < RR; c2++) {
            float d = sq[c2 * 72 + t] - mu;
            var += d * d;
        }
        var *= (1.f / RR);
        float rs = rsqrtf(var + 1e-5f);
#pragma unroll
        for (int c2 = 0; c2 < RR; c2++) {
            float val = (sq[c2 * 72 + t] - mu) * rs * slw[c2] + slb[c2];
            sk[c2 * 72 + t] = val * sv[c2 * 72 + t];
        }
    }
    __syncthreads();

    int o = t >> 3, g = t & 7;
    float a2[8];
#pragma unroll
    for (int j = 0; j < 8; j++) a2[j] = 0.f;
#pragma unroll
    for (int c2 = 0; c2 < RR; c2++) {
        float w = spw[o * 33 + c2];
        float4 v0 = *(const float4*)&sk[c2 * 72 + g * 8];
        float4 v1 = *(const float4*)&sk[c2 * 72 + g * 8 + 4];
        a2[0] += w * v0.x; a2[1] += w * v0.y; a2[2] += w * v0.z; a2[3] += w * v0.w;
        a2[4] += w * v1.x; a2[5] += w * v1.y; a2[6] += w * v1.z; a2[7] += w * v1.w;
    }
    float bias = spb[o];
    float* dst = &d_attb[pair][o][(size_t)(r0 + g) * WW + c0];
    *(float4*)dst       = make_float4(a2[0] + bias, a2[1] + bias, a2[2] + bias, a2[3] + bias);
    *(float4*)(dst + 4) = make_float4(a2[4] + bias, a2[5] + bias, a2[6] + bias, a2[7] + bias);
}

// ---------------- K6: combine, cc-packed f32x2, lane = pixel ----------------
__global__ __launch_bounds__(256) void k_out(const float* __restrict__ x,
                                             const float* __restrict__ p2,
                                             float* __restrict__ out) {
    __shared__ float ws[DIMC][64];
    int b = blockIdx.y;
    int e1 = d_topidx[b][0], e2 = d_topidx[b][1];
    float g1 = d_gates[b][e1], g2 = d_gates[b][e2];
    float gs = d_gatesum[b];
    int t = threadIdx.x;
    int px = blockIdx.x * 256 + t;

    for (int i = t; i < DIMC * 64; i += 256) {
        int o = i >> 6, cc = i & 63;
        int e = (cc < RR) ? e1 : e2;
        ws[o][cc] = p2[((size_t)e * DIMC + o) * RR + (cc & 31)];
    }

    ull av[32];
    {
        int pr1 = b * EE + e1, pr2 = b * EE + e2;
#pragma unroll
        for (int i = 0; i < 16; i++) {
            float f0 = g1 * d_attb[pr1][2 * i][px] * d_gact[pr1][2 * i][px];
            float f1 = g1 * d_attb[pr1][2 * i + 1][px] * d_gact[pr1][2 * i + 1][px];
            av[i] = pk2(f0, f1);
        }
#pragma unroll
        for (int i = 0; i < 16; i++) {
            float f0 = g2 * d_attb[pr2][2 * i][px] * d_gact[pr2][2 * i][px];
            float f1 = g2 * d_attb[pr2][2 * i + 1][px] * d_gact[pr2][2 * i + 1][px];
            av[16 + i] = pk2(f0, f1);
        }
    }
    __syncthreads();

    const float* xb = x + (size_t)b * DIMC * HWPX + px;
    float* ob = out + (size_t)b * DIMC * HWPX + px;
    for (int o = 0; o < DIMC; o++) {
        const ulonglong2* wrow = (const ulonglong2*)&ws[o][0];
        ull a0 = 0ull, a1 = 0ull;
#pragma unroll
        for (int i = 0; i < 16; i++) {
            ulonglong2 w = wrow[i];
            fma2(a0, av[2 * i], w.x);
            fma2(a1, av[2 * i + 1], w.y);
        }
        float2 r0 = upk(a0), r1 = upk(a1);
        float s = (r0.x + r0.y) + (r1.x + r1.y);
        ob[(size_t)o * HWPX] = s + gs * xb[(size_t)o * HWPX];
    }
}

// ---------------- launch ----------------
extern "C" void kernel_launch(void* const* d_in, const int* in_sizes, int n_in,
                              void* d_out, int out_size) {
    const float* x      = (const float*)d_in[0];
    const float* shin   = (const float*)d_in[1];
    const float* femb   = (const float*)d_in[2];
    const float* noise  = (const float*)d_in[3];
    const float* gate_w = (const float*)d_in[4];
    const float* fgw    = (const float*)d_in[5];
    const float* p0     = (const float*)d_in[6];
    const float* p1     = (const float*)d_in[7];
    const float* p2     = (const float*)d_in[8];
    const float* q_w    = (const float*)d_in[9];
    const float* q_dw   = (const float*)d_in[10];
    const float* kv_w   = (const float*)d_in[11];
    const float* kv_dw  = (const float*)d_in[12];
    const float* ln_w   = (const float*)d_in[13];
    const float* ln_b   = (const float*)d_in[14];
    const float* po_w   = (const float*)d_in[15];
    const float* po_b   = (const float*)d_in[16];
    float* out = (float*)d_out;

    k_pool<<<BB * DIMC, 256>>>(x);
    k_gate<<<1, 32>>>(femb, noise, gate_w, fgw);
    k_compose<<<EE, 256>>>(p0, q_w, kv_w);
    k_pre<<<dim3(HWPX / PXT, NPAIR), 256>>>(x, shin, p1);
    k_dw<<<dim3(16, 96, NPAIR), 256>>>(q_dw, kv_dw);
    k_patch<<<dim3(256, NPAIR), 256>>>(ln_w, ln_b, po_w, po_b);
    k_out<<<dim3(HWPX / 256, BB), 256>>>(x, p2, out);
}

// round 11
// speedup vs baseline: 1.0544x; 1.0544x over previous
#include <cuda_runtime.h>
#include <math.h>

#define BB 16
#define EE 4
#define DIMC 64
#define RR 32
#define HH 128
#define WW 128
#define HWPX (HH*WW)
#define FREQN 64
#define NPAIR (BB*EE)

typedef unsigned long long ull;

// ---- packed f32x2 helpers (sm_100+) ----
__device__ __forceinline__ ull pk2(float lo, float hi) {
    ull r;
    asm("mov.b64 %0, {%1, %2};" : "=l"(r) : "f"(lo), "f"(hi));
    return r;
}
__device__ __forceinline__ void fma2(ull& d, ull a, ull b) {
    asm("fma.rn.f32x2 %0, %1, %2, %0;" : "+l"(d) : "l"(a), "l"(b));
}
__device__ __forceinline__ float2 upk(ull v) {
    float lo, hi;
    asm("mov.b64 {%0, %1}, %2;" : "=f"(lo), "=f"(hi) : "l"(v));
    return make_float2(lo, hi);
}

// ---------------- scratch (device globals) ----------------
__device__ float d_pooled[BB][DIMC];
__device__ float d_gates[BB][EE];
__device__ float d_gatesum[BB];
__device__ int   d_topidx[BB][2];
__device__ float d_qc[EE][RR][DIMC];
__device__ float d_kvc[EE][2*RR][DIMC];
__device__ float d_qpre[NPAIR][RR][HWPX];
__device__ float d_kvpre[NPAIR][2*RR][HWPX];
__device__ float d_qb[NPAIR][RR][HWPX];
__device__ float d_kb[NPAIR][RR][HWPX];
__device__ float d_vb[NPAIR][RR][HWPX];
__device__ float d_gact[NPAIR][RR][HWPX];
__device__ float d_attb[NPAIR][RR][HWPX];

// ---------------- K0: pooled mean ----------------
__global__ void k_pool(const float* __restrict__ x) {
    int bc = blockIdx.x;
    const float* p = x + (size_t)bc * HWPX;
    float s = 0.f;
    for (int i = threadIdx.x; i < HWPX; i += 256) s += p[i];
    __shared__ float sm[256];
    sm[threadIdx.x] = s;
    __syncthreads();
    for (int o = 128; o > 0; o >>= 1) {
        if (threadIdx.x < o) sm[threadIdx.x] += sm[threadIdx.x + o];
        __syncthreads();
    }
    if (threadIdx.x == 0) d_pooled[bc / DIMC][bc % DIMC] = sm[0] * (1.f / (float)HWPX);
}

// ---------------- K1: gating ----------------
__global__ void k_gate(const float* __restrict__ freq_emb, const float* __restrict__ noise,
                       const float* __restrict__ gate_w, const float* __restrict__ fgw) {
    int b = threadIdx.x;
    if (b >= BB) return;
    float lg[EE];
    for (int e = 0; e < EE; e++) {
        float s = 0.f;
        for (int d = 0; d < DIMC; d++) s += d_pooled[b][d] * gate_w[e * DIMC + d];
        for (int f = 0; f < FREQN; f++) s += freq_emb[b * FREQN + f] * fgw[e * FREQN + f];
        lg[e] = s + noise[b * EE + e] * (1.0f / (float)EE);
    }
    float mx = lg[0];
    for (int e = 1; e < EE; e++) mx = fmaxf(mx, lg[e]);
    float se = 0.f, sc[EE];
    for (int e = 0; e < EE; e++) { sc[e] = expf(lg[e] - mx); se += sc[e]; }
    for (int e = 0; e < EE; e++) sc[e] /= se;
    int i1 = 0;
    for (int e = 1; e < EE; e++) if (sc[e] > sc[i1]) i1 = e;
    int i2 = -1;
    for (int e = 0; e < EE; e++) {
        if (e == i1) continue;
        if (i2 < 0 || sc[e] > sc[i2]) i2 = e;
    }
    for (int e = 0; e < EE; e++) d_gates[b][e] = (e == i1 || e == i2) ? sc[e] : 0.f;
    d_gatesum[b] = sc[i1] + sc[i2];
    d_topidx[b][0] = i1;
    d_topidx[b][1] = i2;
}

// ---------------- K2: compose q_w@p0, kv_w@p0 ----------------
__global__ void k_compose(const float* __restrict__ p0, const float* __restrict__ q_w,
                          const float* __restrict__ kv_w) {
    int e = blockIdx.x;
    __shared__ float sp0[RR][DIMC];
    for (int i = threadIdx.x; i < RR * DIMC; i += 256)
        sp0[i / DIMC][i % DIMC] = p0[e * RR * DIMC + i];
    __syncthreads();
    for (int i = threadIdx.x; i < RR * DIMC; i += 256) {
        int o = i / DIMC, d = i % DIMC;
        float s = 0.f;
        for (int c = 0; c < RR; c++) s += q_w[(e * RR + o) * RR + c] * sp0[c][d];
        d_qc[e][o][d] = s;
    }
    for (int i = threadIdx.x; i < 2 * RR * DIMC; i += 256) {
        int o = i / DIMC, d = i % DIMC;
        float s = 0.f;
        for (int c = 0; c < RR; c++) s += kv_w[(e * 2 * RR + o) * RR + c] * sp0[c][d];
        d_kvc[e][o][d] = s;
    }
}

// ---------------- K3: per-pixel matmuls, d-packed f32x2 (R4 version) ----------------
// lane = pixel (coalesced), x held in registers, weights broadcast from smem.
__global__ __launch_bounds__(256) void k_pre(const float* __restrict__ x,
                                             const float* __restrict__ shin,
                                             const float* __restrict__ p1) {
    __shared__ float ws[96][DIMC];   // 24KB, natural [o][d] layout
    int pair = blockIdx.y;
    int b = pair / EE, e = pair % EE;
    if (d_gates[b][e] == 0.f) return;
    int t = threadIdx.x;
    int px = blockIdx.x * 256 + t;

    for (int i = t; i < 96 * DIMC; i += 256) {
        int o = i >> 6, d = i & 63;
        ws[o][d] = (o < RR) ? d_qc[e][o][d] : d_kvc[e][o - RR][d];
    }

    ull xp[32];
    {
        const float* xb = x + (size_t)b * DIMC * HWPX + px;
#pragma unroll
        for (int dp = 0; dp < 32; dp++)
            xp[dp] = pk2(xb[(size_t)(2 * dp) * HWPX], xb[(size_t)(2 * dp + 1) * HWPX]);
    }
    __syncthreads();

    for (int o = 0; o < 96; o++) {
        const ulonglong2* wrow = (const ulonglong2*)&ws[o][0];
        ull a0 = 0ull, a1 = 0ull;
#pragma unroll
        for (int i = 0; i < 16; i++) {
            ulonglong2 w = wrow[i];
            fma2(a0, xp[2 * i], w.x);
            fma2(a1, xp[2 * i + 1], w.y);
        }
        float2 r0 = upk(a0), r1 = upk(a1);
        float s = (r0.x + r0.y) + (r1.x + r1.y);
        float* dst = (o < RR) ? &d_qpre[pair][o][0] : &d_kvpre[pair][o - RR][0];
        dst[px] = s;
    }
    __syncthreads();

    for (int i = t; i < RR * DIMC; i += 256) {
        int o = i >> 6, d = i & 63;
        ws[o][d] = p1[(e * RR + o) * DIMC + d];
    }
    {
        const float* sb = shin + (size_t)b * DIMC * HWPX + px;
#pragma unroll
        for (int dp = 0; dp < 32; dp++)
            xp[dp] = pk2(sb[(size_t)(2 * dp) * HWPX], sb[(size_t)(2 * dp + 1) * HWPX]);
    }
    __syncthreads();

    for (int o = 0; o < RR; o++) {
        const ulonglong2* wrow = (const ulonglong2*)&ws[o][0];
        ull a0 = 0ull, a1 = 0ull;
#pragma unroll
        for (int i = 0; i < 16; i++) {
            ulonglong2 w = wrow[i];
            fma2(a0, xp[2 * i], w.x);
            fma2(a1, xp[2 * i + 1], w.y);
        }
        float2 r0 = upk(a0), r1 = upk(a1);
        float s = (r0.x + r0.y) + (r1.x + r1.y);
        d_gact[pair][o][px] = s / (1.f + expf(-s));
    }
}

// ---------------- K4: depthwise conv, 32x32 tiles, row-pair packed f32x2 ----------------
template <int R>
__device__ __forceinline__ void dwconv_tile(const float* __restrict__ src,
                                            const float* __restrict__ w,
                                            float* __restrict__ dst,
                                            int ty, int tx, float* tile) {
    const int KS = 2 * R + 1, TW = 32 + 2 * R;
    int t = threadIdx.x;
    for (int i = t; i < TW * TW; i += 256) {
        int iy = i / TW, ix = i % TW;
        int gy = ty + iy - R, gx = tx + ix - R;
        tile[i] = (gy >= 0 && gy < HH && gx >= 0 && gx < WW) ? src[gy * WW + gx] : 0.f;
    }
    float wr[KS * KS];
#pragma unroll
    for (int i = 0; i < KS * KS; i++) wr[i] = w[i];
    __syncthreads();
    int lx = t % 32, y0 = (t / 32) * 4;
    ull acc01 = 0ull, acc23 = 0ull;   // output rows {y0,y0+1}, {y0+2,y0+3}
#pragma unroll
    for (int dx = 0; dx < KS; dx++) {
        float col[4 + 2 * R];
#pragma unroll
        for (int r = 0; r < 4 + 2 * R; r++) col[r] = tile[(y0 + r) * TW + lx + dx];
        ull colp[3 + 2 * R];
#pragma unroll
        for (int j = 0; j < 3 + 2 * R; j++) colp[j] = pk2(col[j], col[j + 1]);
#pragma unroll
        for (int dy = 0; dy < KS; dy++) {
            float wv = wr[dy * KS + dx];
            ull wp = pk2(wv, wv);
            fma2(acc01, wp, colp[dy]);
            fma2(acc23, wp, colp[dy + 2]);
        }
    }
    float2 r01 = upk(acc01), r23 = upk(acc23);
    dst[(ty + y0 + 0) * WW + tx + lx] = r01.x;
    dst[(ty + y0 + 1) * WW + tx + lx] = r01.y;
    dst[(ty + y0 + 2) * WW + tx + lx] = r23.x;
    dst[(ty + y0 + 3) * WW + tx + lx] = r23.y;
}

__global__ __launch_bounds__(256) void k_dw(const float* __restrict__ q_dw,
                                            const float* __restrict__ kv_dw) {
    int pair = blockIdx.z;
    int b = pair / EE, e = pair % EE;
    if (d_gates[b][e] == 0.f) return;
    __shared__ float tile[38 * 38];
    int ch = blockIdx.y;
    int ty = (blockIdx.x >> 2) * 32, tx = (blockIdx.x & 3) * 32;
    if (ch < RR) {
        dwconv_tile<1>(&d_qpre[pair][ch][0], q_dw + (size_t)(e * RR + ch) * 9,
                       &d_qb[pair][ch][0], ty, tx, tile);
    } else {
        int c = ch - RR;
        float* dst = (c < RR) ? &d_kb[pair][c][0] : &d_vb[pair][c - RR][0];
        dwconv_tile<3>(&d_kvpre[pair][c][0], kv_dw + (size_t)(e * 2 * RR + c) * 49,
                       dst, ty, tx, tile);
    }
}

// ---------------- K5: 8x8 circular conv + LN + *v + po conv (f32x2) ----------------
__global__ __launch_bounds__(256) void k_patch(const float* __restrict__ ln_w,
                                               const float* __restrict__ ln_b,
                                               const float* __restrict__ po_w,
                                               const float* __restrict__ po_b) {
    int pair = blockIdx.y;
    int b = pair / EE, e = pair % EE;
    if (d_gates[b][e] == 0.f) return;
    int patch = blockIdx.x;
    int r0 = (patch / 16) * 8, c0 = (patch % 16) * 8;
    int t = threadIdx.x;

    __shared__ __align__(16) float sq[RR * 72];
    __shared__ __align__(16) float sk[RR * 72];
    __shared__ __align__(16) float sv[RR * 72];
    __shared__ float spw[RR * 33];
    __shared__ float spb[RR], slw[RR], slb[RR];

    {
        int c = t >> 3, pr = t & 7;
        size_t off = (size_t)(r0 + pr) * WW + c0;
        const float* qp = &d_qb[pair][c][off];
        const float* kp = &d_kb[pair][c][off];
        const float* vp = &d_vb[pair][c][off];
        *(float4*)&sq[c * 72 + pr * 8]     = *(const float4*)qp;
        *(float4*)&sq[c * 72 + pr * 8 + 4] = *(const float4*)(qp + 4);
        *(float4*)&sk[c * 72 + pr * 8]     = *(const float4*)kp;
        *(float4*)&sk[c * 72 + pr * 8 + 4] = *(const float4*)(kp + 4);
        *(float4*)&sv[c * 72 + pr * 8]     = *(const float4*)vp;
        *(float4*)&sv[c * 72 + pr * 8 + 4] = *(const float4*)(vp + 4);
    }
    for (int i = t; i < RR * RR; i += 256)
        spw[(i / RR) * 33 + (i % RR)] = po_w[(size_t)e * RR * RR + i];
    if (t < RR) {
        spb[t] = po_b[e * RR + t];
        slw[t] = ln_w[e * RR + t];
        slb[t] = ln_b[e * RR + t];
    }
    __syncthreads();

    // circular conv: thread (c, i) computes output row i; packed output-col pairs.
    int c = t >> 3, i = t & 7;
    ull accp[4];
#pragma unroll
    for (int jp = 0; jp < 4; jp++) accp[jp] = 0ull;
#pragma unroll
    for (int u = 0; u < 8; u++) {
        float4 qa = *(const float4*)&sq[c * 72 + u * 8];
        float4 qb4 = *(const float4*)&sq[c * 72 + u * 8 + 4];
        float qv[8] = {qa.x, qa.y, qa.z, qa.w, qb4.x, qb4.y, qb4.z, qb4.w};
        ull qs[8];
#pragma unroll
        for (int v = 0; v < 8; v++) qs[v] = pk2(qv[v], qv[v]);
        int kr = (i - u) & 7;
        float4 ka = *(const float4*)&sk[c * 72 + kr * 8];
        float4 kb4 = *(const float4*)&sk[c * 72 + kr * 8 + 4];
        float kv[8] = {ka.x, ka.y, ka.z, ka.w, kb4.x, kb4.y, kb4.z, kb4.w};
        ull kp[8];
#pragma unroll
        for (int m = 0; m < 8; m++) kp[m] = pk2(kv[m], kv[(m + 1) & 7]);
#pragma unroll
        for (int v = 0; v < 8; v++)
#pragma unroll
            for (int jp = 0; jp < 4; jp++)
                fma2(accp[jp], qs[v], kp[(2 * jp - v) & 7]);
    }
    __syncthreads();
    {
        ull* dstp = (ull*)&sq[c * 72 + i * 8];
#pragma unroll
        for (int jp = 0; jp < 4; jp++) dstp[jp] = accp[jp];
    }
    __syncthreads();

    // LN over channels per pixel, * v  (result into sk)
    if (t < 64) {
        float mu = 0.f;
#pragma unroll
        for (int c2 = 0; c2 < RR; c2++) mu += sq[c2 * 72 + t];
        mu *= (1.f / RR);
        float var = 0.f;
#pragma unroll
        for (int c2 = 0; c2 < RR; c2++) {
            float d = sq[c2 * 72 + t] - mu;
            var += d * d;
        }
        var *= (1.f / RR);
        float rs = rsqrtf(var + 1e-5f);
#pragma unroll
        for (int c2 = 0; c2 < RR; c2++) {
            float val = (sq[c2 * 72 + t] - mu) * rs * slw[c2] + slb[c2];
            sk[c2 * 72 + t] = val * sv[c2 * 72 + t];
        }
    }
    __syncthreads();

    // po conv: thread (o, g); pixel pairs natively packed.
    int o = t >> 3, g = t & 7;
    ull a2p[4];
#pragma unroll
    for (int jp = 0; jp < 4; jp++) a2p[jp] = 0ull;
#pragma unroll
    for (int c2 = 0; c2 < RR; c2++) {
        float w = spw[o * 33 + c2];
        ull wp = pk2(w, w);
        const ulonglong2* vp = (const ulonglong2*)&sk[c2 * 72 + g * 8];
        ulonglong2 v01 = vp[0], v23 = vp[1];
        fma2(a2p[0], wp, v01.x);
        fma2(a2p[1], wp, v01.y);
        fma2(a2p[2], wp, v23.x);
        fma2(a2p[3], wp, v23.y);
    }
    float bias = spb[o];
    float2 q0 = upk(a2p[0]), q1 = upk(a2p[1]), q2 = upk(a2p[2]), q3 = upk(a2p[3]);
    float* dst = &d_attb[pair][o][(size_t)(r0 + g) * WW + c0];
    *(float4*)dst       = make_float4(q0.x + bias, q0.y + bias, q1.x + bias, q1.y + bias);
    *(float4*)(dst + 4) = make_float4(q2.x + bias, q2.y + bias, q3.x + bias, q3.y + bias);
}

// ---------------- K6: combine, cc-packed f32x2, lane = pixel ----------------
__global__ __launch_bounds__(256) void k_out(const float* __restrict__ x,
                                             const float* __restrict__ p2,
                                             float* __restrict__ out) {
    __shared__ float ws[DIMC][64];
    int b = blockIdx.y;
    int e1 = d_topidx[b][0], e2 = d_topidx[b][1];
    float g1 = d_gates[b][e1], g2 = d_gates[b][e2];
    float gs = d_gatesum[b];
    int t = threadIdx.x;
    int px = blockIdx.x * 256 + t;

    for (int i = t; i < DIMC * 64; i += 256) {
        int o = i >> 6, cc = i & 63;
        int e = (cc < RR) ? e1 : e2;
        ws[o][cc] = p2[((size_t)e * DIMC + o) * RR + (cc & 31)];
    }

    ull av[32];
    {
        int pr1 = b * EE + e1, pr2 = b * EE + e2;
#pragma unroll
        for (int i = 0; i < 16; i++) {
            float f0 = g1 * d_attb[pr1][2 * i][px] * d_gact[pr1][2 * i][px];
            float f1 = g1 * d_attb[pr1][2 * i + 1][px] * d_gact[pr1][2 * i + 1][px];
            av[i] = pk2(f0, f1);
        }
#pragma unroll
        for (int i = 0; i < 16; i++) {
            float f0 = g2 * d_attb[pr2][2 * i][px] * d_gact[pr2][2 * i][px];
            float f1 = g2 * d_attb[pr2][2 * i + 1][px] * d_gact[pr2][2 * i + 1][px];
            av[16 + i] = pk2(f0, f1);
        }
    }
    __syncthreads();

    const float* xb = x + (size_t)b * DIMC * HWPX + px;
    float* ob = out + (size_t)b * DIMC * HWPX + px;
    for (int o = 0; o < DIMC; o++) {
        const ulonglong2* wrow = (const ulonglong2*)&ws[o][0];
        ull a0 = 0ull, a1 = 0ull;
#pragma unroll
        for (int i = 0; i < 16; i++) {
            ulonglong2 w = wrow[i];
            fma2(a0, av[2 * i], w.x);
            fma2(a1, av[2 * i + 1], w.y);
        }
        float2 r0 = upk(a0), r1 = upk(a1);
        float s = (r0.x + r0.y) + (r1.x + r1.y);
        ob[(size_t)o * HWPX] = s + gs * xb[(size_t)o * HWPX];
    }
}

// ---------------- launch ----------------
extern "C" void kernel_launch(void* const* d_in, const int* in_sizes, int n_in,
                              void* d_out, int out_size) {
    const float* x      = (const float*)d_in[0];
    const float* shin   = (const float*)d_in[1];
    const float* femb   = (const float*)d_in[2];
    const float* noise  = (const float*)d_in[3];
    const float* gate_w = (const float*)d_in[4];
    const float* fgw    = (const float*)d_in[5];
    const float* p0     = (const float*)d_in[6];
    const float* p1     = (const float*)d_in[7];
    const float* p2     = (const float*)d_in[8];
    const float* q_w    = (const float*)d_in[9];
    const float* q_dw   = (const float*)d_in[10];
    const float* kv_w   = (const float*)d_in[11];
    const float* kv_dw  = (const float*)d_in[12];
    const float* ln_w   = (const float*)d_in[13];
    const float* ln_b   = (const float*)d_in[14];
    const float* po_w   = (const float*)d_in[15];
    const float* po_b   = (const float*)d_in[16];
    float* out = (float*)d_out;

    k_pool<<<BB * DIMC, 256>>>(x);
    k_gate<<<1, 32>>>(femb, noise, gate_w, fgw);
    k_compose<<<EE, 256>>>(p0, q_w, kv_w);
    k_pre<<<dim3(HWPX / 256, NPAIR), 256>>>(x, shin, p1);
    k_dw<<<dim3(16, 96, NPAIR), 256>>>(q_dw, kv_dw);
    k_patch<<<dim3(256, NPAIR), 256>>>(ln_w, ln_b, po_w, po_b);
    k_out<<<dim3(HWPX / 256, BB), 256>>>(x, p2, out);
}

// round 12
// speedup vs baseline: 1.1480x; 1.0888x over previous
#include <cuda_runtime.h>
#include <math.h>

#define BB 16
#define EE 4
#define DIMC 64
#define RR 32
#define HH 128
#define WW 128
#define HWPX (HH*WW)
#define FREQN 64
#define NPAIR (BB*EE)

typedef unsigned long long ull;

// ---- packed f32x2 helpers (sm_100+) ----
__device__ __forceinline__ ull pk2(float lo, float hi) {
    ull r;
    asm("mov.b64 %0, {%1, %2};" : "=l"(r) : "f"(lo), "f"(hi));
    return r;
}
__device__ __forceinline__ void fma2(ull& d, ull a, ull b) {
    asm("fma.rn.f32x2 %0, %1, %2, %0;" : "+l"(d) : "l"(a), "l"(b));
}
__device__ __forceinline__ float2 upk(ull v) {
    float lo, hi;
    asm("mov.b64 {%0, %1}, %2;" : "=f"(lo), "=f"(hi) : "l"(v));
    return make_float2(lo, hi);
}

// ---------------- scratch (device globals) ----------------
__device__ float d_pooled[BB][DIMC];
__device__ float d_gates[BB][EE];
__device__ float d_gatesum[BB];
__device__ int   d_topidx[BB][2];
__device__ float d_qc[EE][RR][DIMC];
__device__ float d_kvc[EE][2*RR][DIMC];
__device__ float d_qpre[NPAIR][RR][HWPX];
__device__ float d_kvpre[NPAIR][2*RR][HWPX];
__device__ float d_gact[NPAIR][RR][HWPX];
__device__ float d_attb[NPAIR][RR][HWPX];

// ---------------- K0: pooled mean ----------------
__global__ void k_pool(const float* __restrict__ x) {
    int bc = blockIdx.x;
    const float* p = x + (size_t)bc * HWPX;
    float s = 0.f;
    for (int i = threadIdx.x * 4; i < HWPX; i += 1024) {
        float4 v = *(const float4*)&p[i];
        s += (v.x + v.y) + (v.z + v.w);
    }
    __shared__ float sm[256];
    sm[threadIdx.x] = s;
    __syncthreads();
    for (int o = 128; o > 0; o >>= 1) {
        if (threadIdx.x < o) sm[threadIdx.x] += sm[threadIdx.x + o];
        __syncthreads();
    }
    if (threadIdx.x == 0) d_pooled[bc / DIMC][bc % DIMC] = sm[0] * (1.f / (float)HWPX);
}

// ---------------- K1: gating ----------------
__global__ void k_gate(const float* __restrict__ freq_emb, const float* __restrict__ noise,
                       const float* __restrict__ gate_w, const float* __restrict__ fgw) {
    int b = threadIdx.x;
    if (b >= BB) return;
    float lg[EE];
    for (int e = 0; e < EE; e++) {
        float s = 0.f;
        for (int d = 0; d < DIMC; d++) s += d_pooled[b][d] * gate_w[e * DIMC + d];
        for (int f = 0; f < FREQN; f++) s += freq_emb[b * FREQN + f] * fgw[e * FREQN + f];
        lg[e] = s + noise[b * EE + e] * (1.0f / (float)EE);
    }
    float mx = lg[0];
    for (int e = 1; e < EE; e++) mx = fmaxf(mx, lg[e]);
    float se = 0.f, sc[EE];
    for (int e = 0; e < EE; e++) { sc[e] = expf(lg[e] - mx); se += sc[e]; }
    for (int e = 0; e < EE; e++) sc[e] /= se;
    int i1 = 0;
    for (int e = 1; e < EE; e++) if (sc[e] > sc[i1]) i1 = e;
    int i2 = -1;
    for (int e = 0; e < EE; e++) {
        if (e == i1) continue;
        if (i2 < 0 || sc[e] > sc[i2]) i2 = e;
    }
    for (int e = 0; e < EE; e++) d_gates[b][e] = (e == i1 || e == i2) ? sc[e] : 0.f;
    d_gatesum[b] = sc[i1] + sc[i2];
    d_topidx[b][0] = i1;
    d_topidx[b][1] = i2;
}

// ---------------- K2: compose q_w@p0, kv_w@p0 ----------------
__global__ void k_compose(const float* __restrict__ p0, const float* __restrict__ q_w,
                          const float* __restrict__ kv_w) {
    int e = blockIdx.x;
    __shared__ float sp0[RR][DIMC];
    for (int i = threadIdx.x; i < RR * DIMC; i += 256)
        sp0[i / DIMC][i % DIMC] = p0[e * RR * DIMC + i];
    __syncthreads();
    for (int i = threadIdx.x; i < RR * DIMC; i += 256) {
        int o = i / DIMC, d = i % DIMC;
        float s = 0.f;
        for (int c = 0; c < RR; c++) s += q_w[(e * RR + o) * RR + c] * sp0[c][d];
        d_qc[e][o][d] = s;
    }
    for (int i = threadIdx.x; i < 2 * RR * DIMC; i += 256) {
        int o = i / DIMC, d = i % DIMC;
        float s = 0.f;
        for (int c = 0; c < RR; c++) s += kv_w[(e * 2 * RR + o) * RR + c] * sp0[c][d];
        d_kvc[e][o][d] = s;
    }
}

// ---------------- K3: per-pixel matmuls, d-packed f32x2 (proven 264us version) ----------------
__global__ __launch_bounds__(256) void k_pre(const float* __restrict__ x,
                                             const float* __restrict__ shin,
                                             const float* __restrict__ p1) {
    __shared__ float ws[96][DIMC];
    int pair = blockIdx.y;
    int b = pair / EE, e = pair % EE;
    if (d_gates[b][e] == 0.f) return;
    int t = threadIdx.x;
    int px = blockIdx.x * 256 + t;

    for (int i = t; i < 96 * DIMC; i += 256) {
        int o = i >> 6, d = i & 63;
        ws[o][d] = (o < RR) ? d_qc[e][o][d] : d_kvc[e][o - RR][d];
    }

    ull xp[32];
    {
        const float* xb = x + (size_t)b * DIMC * HWPX + px;
#pragma unroll
        for (int dp = 0; dp < 32; dp++)
            xp[dp] = pk2(xb[(size_t)(2 * dp) * HWPX], xb[(size_t)(2 * dp + 1) * HWPX]);
    }
    __syncthreads();

    for (int o = 0; o < 96; o++) {
        const ulonglong2* wrow = (const ulonglong2*)&ws[o][0];
        ull a0 = 0ull, a1 = 0ull;
#pragma unroll
        for (int i = 0; i < 16; i++) {
            ulonglong2 w = wrow[i];
            fma2(a0, xp[2 * i], w.x);
            fma2(a1, xp[2 * i + 1], w.y);
        }
        float2 r0 = upk(a0), r1 = upk(a1);
        float s = (r0.x + r0.y) + (r1.x + r1.y);
        float* dst = (o < RR) ? &d_qpre[pair][o][0] : &d_kvpre[pair][o - RR][0];
        dst[px] = s;
    }
    __syncthreads();

    for (int i = t; i < RR * DIMC; i += 256) {
        int o = i >> 6, d = i & 63;
        ws[o][d] = p1[(e * RR + o) * DIMC + d];
    }
    {
        const float* sb = shin + (size_t)b * DIMC * HWPX + px;
#pragma unroll
        for (int dp = 0; dp < 32; dp++)
            xp[dp] = pk2(sb[(size_t)(2 * dp) * HWPX], sb[(size_t)(2 * dp + 1) * HWPX]);
    }
    __syncthreads();

    for (int o = 0; o < RR; o++) {
        const ulonglong2* wrow = (const ulonglong2*)&ws[o][0];
        ull a0 = 0ull, a1 = 0ull;
#pragma unroll
        for (int i = 0; i < 16; i++) {
            ulonglong2 w = wrow[i];
            fma2(a0, xp[2 * i], w.x);
            fma2(a1, xp[2 * i + 1], w.y);
        }
        float2 r0 = upk(a0), r1 = upk(a1);
        float s = (r0.x + r0.y) + (r1.x + r1.y);
        d_gact[pair][o][px] = s / (1.f + expf(-s));
    }
}

// ---------------- K4+K5 fused: dwconv + 8x8 circular conv + LN + *v + po conv ----------------
// Block = (pair, 16x16 region). Warp-private dwconv into smem patch buffers;
// all patch-domain math stays in shared memory. Eliminates qb/kb/vb entirely.
// Smem layout per channel: 4 patches x 68-float slots (8x8 patch + 4 pad).

template <int R>
__device__ __forceinline__ void warp_dwconv(const float* __restrict__ src,
                                            const float* __restrict__ wv,
                                            float* __restrict__ wt,
                                            float* __restrict__ dstc,
                                            int ry0, int rx0, int lane) {
    const int KS = 2 * R + 1, TW = 16 + 2 * R, TT = TW * TW;
    for (int idx = lane; idx < TT; idx += 32) {
        int iy = idx / TW, ix = idx % TW;
        int gy = ry0 + iy - R, gx = rx0 + ix - R;
        wt[idx] = (gy >= 0 && gy < HH && gx >= 0 && gx < WW) ? src[gy * WW + gx] : 0.f;
    }
    __syncwarp();
    int col = lane & 15, rh = lane >> 4;
    ull acc[4] = {0ull, 0ull, 0ull, 0ull};
#pragma unroll
    for (int dx = 0; dx < KS; dx++) {
        float colv[8 + 2 * R];
#pragma unroll
        for (int r = 0; r < 8 + 2 * R; r++) colv[r] = wt[(rh * 8 + r) * TW + col + dx];
#pragma unroll
        for (int dy = 0; dy < KS; dy++) {
            float w = wv[dy * KS + dx];
            ull wp = pk2(w, w);
#pragma unroll
            for (int k2 = 0; k2 < 4; k2++)
                fma2(acc[k2], wp, pk2(colv[dy + 2 * k2], colv[dy + 2 * k2 + 1]));
        }
    }
    int pbase = (rh * 2 + (col >> 3)) * 68;
    int j = col & 7;
#pragma unroll
    for (int k2 = 0; k2 < 4; k2++) {
        float2 v = upk(acc[k2]);
        dstc[pbase + (2 * k2) * 8 + j]     = v.x;
        dstc[pbase + (2 * k2 + 1) * 8 + j] = v.y;
    }
    __syncwarp();
}

__global__ __launch_bounds__(256) void k_dwpatch(const float* __restrict__ q_dw,
                                                const float* __restrict__ kv_dw,
                                                const float* __restrict__ ln_w,
                                                const float* __restrict__ ln_b,
                                                const float* __restrict__ po_w,
                                                const float* __restrict__ po_b) {
    int pair = blockIdx.y;
    int b = pair / EE, e = pair % EE;
    if (d_gates[b][e] == 0.f) return;

    extern __shared__ float dsm[];
    float* rq   = dsm;                  // 32*272  (q results -> circular-conv results)
    float* rk   = rq + 32 * 272;        // 32*272  (k results -> v results -> LN*v)
    float* wt   = rk + 32 * 272;        // 8*488   (per-warp conv tiles)
    float* swq  = wt + 8 * 488;         // 32*12
    float* swkv = swq + 32 * 12;        // 64*52
    float* spw  = swkv + 64 * 52;       // 32*33
    float* spb  = spw + 32 * 33;        // 32
    float* slw  = spb + 32;             // 32
    float* slb  = slw + 32;             // 32

    int t = threadIdx.x, w = t >> 5, lane = t & 31;
    int ry0 = (blockIdx.x >> 3) * 16, rx0 = (blockIdx.x & 7) * 16;

    // stage weights
    for (int i = t; i < 32 * 9;  i += 256) swq[(i / 9) * 12 + i % 9]  = q_dw[(size_t)e * 32 * 9 + i];
    for (int i = t; i < 64 * 49; i += 256) swkv[(i / 49) * 52 + i % 49] = kv_dw[(size_t)e * 64 * 49 + i];
    for (int i = t; i < 32 * 32; i += 256) spw[(i >> 5) * 33 + (i & 31)] = po_w[(size_t)e * RR * RR + i];
    if (t < 32) {
        spb[t] = po_b[e * RR + t];
        slw[t] = ln_w[e * RR + t];
        slb[t] = ln_b[e * RR + t];
    }
    __syncthreads();

    float* wt8 = wt + w * 488;

    // phase A: dwconv q (3x3) and k (7x7); 4 channels of each per warp
    for (int j2 = 0; j2 < 4; j2++) {
        int c = w * 4 + j2;
        warp_dwconv<1>(&d_qpre[pair][c][0], &swq[c * 12], wt8, &rq[c * 272], ry0, rx0, lane);
        warp_dwconv<3>(&d_kvpre[pair][c][0], &swkv[c * 52], wt8, &rk[c * 272], ry0, rx0, lane);
    }
    __syncthreads();

    // phase B: 8x8 circular conv per (channel, patch); results held in regs
    int c = t >> 3, i = t & 7;
    ull accp[4][4];
#pragma unroll
    for (int p = 0; p < 4; p++) {
#pragma unroll
        for (int jp = 0; jp < 4; jp++) accp[p][jp] = 0ull;
#pragma unroll
        for (int u = 0; u < 8; u++) {
            float4 qa  = *(const float4*)&rq[c * 272 + p * 68 + u * 8];
            float4 qb4 = *(const float4*)&rq[c * 272 + p * 68 + u * 8 + 4];
            float qv[8] = {qa.x, qa.y, qa.z, qa.w, qb4.x, qb4.y, qb4.z, qb4.w};
            ull qs[8];
#pragma unroll
            for (int v = 0; v < 8; v++) qs[v] = pk2(qv[v], qv[v]);
            int kr = (i - u) & 7;
            float4 ka  = *(const float4*)&rk[c * 272 + p * 68 + kr * 8];
            float4 kb4 = *(const float4*)&rk[c * 272 + p * 68 + kr * 8 + 4];
            float kv[8] = {ka.x, ka.y, ka.z, ka.w, kb4.x, kb4.y, kb4.z, kb4.w};
            ull kp[8];
#pragma unroll
            for (int m = 0; m < 8; m++) kp[m] = pk2(kv[m], kv[(m + 1) & 7]);
#pragma unroll
            for (int v = 0; v < 8; v++)
#pragma unroll
                for (int jp = 0; jp < 4; jp++)
                    fma2(accp[p][jp], qs[v], kp[(2 * jp - v) & 7]);
        }
    }
    __syncthreads();   // all reads of rq (q) and rk (k) done

    // write circular-conv results into rq (overwrite q data)
#pragma unroll
    for (int p = 0; p < 4; p++) {
        ull* dstp = (ull*)&rq[c * 272 + p * 68 + i * 8];
#pragma unroll
        for (int jp = 0; jp < 4; jp++) dstp[jp] = accp[p][jp];
    }

    // phase C: dwconv v (7x7) into rk (k data no longer needed)
    for (int j2 = 0; j2 < 4; j2++) {
        int cv = w * 4 + j2;
        warp_dwconv<3>(&d_kvpre[pair][32 + cv][0], &swkv[(32 + cv) * 52], wt8,
                       &rk[cv * 272], ry0, rx0, lane);
    }
    __syncthreads();

    // phase D: LayerNorm over channels per pixel, multiply by v (into rk)
    {
        int p = t >> 6, pix = t & 63;
        float mu = 0.f;
#pragma unroll
        for (int c2 = 0; c2 < RR; c2++) mu += rq[c2 * 272 + p * 68 + pix];
        mu *= (1.f / RR);
        float var = 0.f;
#pragma unroll
        for (int c2 = 0; c2 < RR; c2++) {
            float d = rq[c2 * 272 + p * 68 + pix] - mu;
            var += d * d;
        }
        var *= (1.f / RR);
        float rs = rsqrtf(var + 1e-5f);
#pragma unroll
        for (int c2 = 0; c2 < RR; c2++) {
            float val = (rq[c2 * 272 + p * 68 + pix] - mu) * rs * slw[c2] + slb[c2];
            rk[c2 * 272 + p * 68 + pix] = val * rk[c2 * 272 + p * 68 + pix];
        }
    }
    __syncthreads();

    // phase E: po conv (32->32) per pixel; write attb
    int o = t >> 3, g = t & 7;
#pragma unroll
    for (int p = 0; p < 4; p++) {
        ull a2p[4] = {0ull, 0ull, 0ull, 0ull};
#pragma unroll
        for (int c2 = 0; c2 < RR; c2++) {
            float wv = spw[o * 33 + c2];
            ull wp = pk2(wv, wv);
            const ulonglong2* vp = (const ulonglong2*)&rk[c2 * 272 + p * 68 + g * 8];
            ulonglong2 v01 = vp[0], v23 = vp[1];
            fma2(a2p[0], wp, v01.x);
            fma2(a2p[1], wp, v01.y);
            fma2(a2p[2], wp, v23.x);
            fma2(a2p[3], wp, v23.y);
        }
        float bias = spb[o];
        float2 q0 = upk(a2p[0]), q1 = upk(a2p[1]), q2 = upk(a2p[2]), q3 = upk(a2p[3]);
        float* dst = &d_attb[pair][o][(size_t)(ry0 + (p >> 1) * 8 + g) * WW + rx0 + (p & 1) * 8];
        *(float4*)dst       = make_float4(q0.x + bias, q0.y + bias, q1.x + bias, q1.y + bias);
        *(float4*)(dst + 4) = make_float4(q2.x + bias, q2.y + bias, q3.x + bias, q3.y + bias);
    }
}

// ---------------- K6: combine, cc-packed f32x2, lane = pixel ----------------
__global__ __launch_bounds__(256) void k_out(const float* __restrict__ x,
                                             const float* __restrict__ p2,
                                             float* __restrict__ out) {
    __shared__ float ws[DIMC][64];
    int b = blockIdx.y;
    int e1 = d_topidx[b][0], e2 = d_topidx[b][1];
    float g1 = d_gates[b][e1], g2 = d_gates[b][e2];
    float gs = d_gatesum[b];
    int t = threadIdx.x;
    int px = blockIdx.x * 256 + t;

    for (int i = t; i < DIMC * 64; i += 256) {
        int o = i >> 6, cc = i & 63;
        int e = (cc < RR) ? e1 : e2;
        ws[o][cc] = p2[((size_t)e * DIMC + o) * RR + (cc & 31)];
    }

    ull av[32];
    {
        int pr1 = b * EE + e1, pr2 = b * EE + e2;
#pragma unroll
        for (int i = 0; i < 16; i++) {
            float f0 = g1 * d_attb[pr1][2 * i][px] * d_gact[pr1][2 * i][px];
            float f1 = g1 * d_attb[pr1][2 * i + 1][px] * d_gact[pr1][2 * i + 1][px];
            av[i] = pk2(f0, f1);
        }
#pragma unroll
        for (int i = 0; i < 16; i++) {
            float f0 = g2 * d_attb[pr2][2 * i][px] * d_gact[pr2][2 * i][px];
            float f1 = g2 * d_attb[pr2][2 * i + 1][px] * d_gact[pr2][2 * i + 1][px];
            av[16 + i] = pk2(f0, f1);
        }
    }
    __syncthreads();

    const float* xb = x + (size_t)b * DIMC * HWPX + px;
    float* ob = out + (size_t)b * DIMC * HWPX + px;
    for (int o = 0; o < DIMC; o++) {
        const ulonglong2* wrow = (const ulonglong2*)&ws[o][0];
        ull a0 = 0ull, a1 = 0ull;
#pragma unroll
        for (int i = 0; i < 16; i++) {
            ulonglong2 w = wrow[i];
            fma2(a0, av[2 * i], w.x);
            fma2(a1, av[2 * i + 1], w.y);
        }
        float2 r0 = upk(a0), r1 = upk(a1);
        float s = (r0.x + r0.y) + (r1.x + r1.y);
        ob[(size_t)o * HWPX] = s + gs * xb[(size_t)o * HWPX];
    }
}

// ---------------- launch ----------------
extern "C" void kernel_launch(void* const* d_in, const int* in_sizes, int n_in,
                              void* d_out, int out_size) {
    const float* x      = (const float*)d_in[0];
    const float* shin   = (const float*)d_in[1];
    const float* femb   = (const float*)d_in[2];
    const float* noise  = (const float*)d_in[3];
    const float* gate_w = (const float*)d_in[4];
    const float* fgw    = (const float*)d_in[5];
    const float* p0     = (const float*)d_in[6];
    const float* p1     = (const float*)d_in[7];
    const float* p2     = (const float*)d_in[8];
    const float* q_w    = (const float*)d_in[9];
    const float* q_dw   = (const float*)d_in[10];
    const float* kv_w   = (const float*)d_in[11];
    const float* kv_dw  = (const float*)d_in[12];
    const float* ln_w   = (const float*)d_in[13];
    const float* ln_b   = (const float*)d_in[14];
    const float* po_w   = (const float*)d_in[15];
    const float* po_b   = (const float*)d_in[16];
    float* out = (float*)d_out;

    // 32*272*2 + 8*488 + 32*12 + 64*52 + 32*33 + 96 floats
    static const int kDPSmem = (32 * 272 * 2 + 8 * 488 + 32 * 12 + 64 * 52 + 32 * 33 + 96) * 4;
    cudaFuncSetAttribute(k_dwpatch, cudaFuncAttributeMaxDynamicSharedMemorySize, kDPSmem);

    k_pool<<<BB * DIMC, 256>>>(x);
    k_gate<<<1, 32>>>(femb, noise, gate_w, fgw);
    k_compose<<<EE, 256>>>(p0, q_w, kv_w);
    k_pre<<<dim3(HWPX / 256, NPAIR), 256>>>(x, shin, p1);
    k_dwpatch<<<dim3(64, NPAIR), 256, kDPSmem>>>(q_dw, kv_dw, ln_w, ln_b, po_w, po_b);
    k_out<<<dim3(HWPX / 256, BB), 256>>>(x, p2, out);
}